// round 13
// baseline (speedup 1.0000x reference)
#include <cuda_runtime.h>
#include <cuda_bf16.h>
#include <cstdint>

#define NGRID 8192
#define NLAYER 24
#define NPERIODS 50
#define NOBS 4096
#define NC 200
#define NPAD 64
#define KSPLIT 8
#define KB (NGRID / KSPLIT)      // 1024 K per CTA
#define KCHUNK 32
#define NCHUNK (KB / KCHUNK)     // 32
#define MT 128
#define NSTAGE 4
#define STAGE_A (MT * 128)           // 128 rows x 128B (32 f32)
#define STAGE_B (NPAD * 128)         // 64 rows x 128B (32 bf16 used)
#define STAGE (STAGE_A + STAGE_B)    // 24576
#define SMEM_TOT (NSTAGE * STAGE)    // 98304 -> 2 CTAs/SM
#define NCTA 256
#define EROWS_PER_CTA 800            // 204800 / 256
#define VREF 3.0f
#define RAYF 0.92f

// ---------------- scratch (no allocation allowed) ----------------
__device__ __nv_bfloat16 g_Rt[NPAD * NGRID];    // [n=64][k=8192] bf16; rows 50..63 zero
__device__ float g_part[KSPLIT * NOBS * NPAD];  // k-split partial s_pred
__device__ int g_flag;                          // dispersion-done counter (memset each launch)

// ---------------- helpers ----------------
__device__ __forceinline__ uint32_t smem_u32(const void* p) {
    uint32_t a;
    asm("{ .reg .u64 t; cvta.to.shared.u64 t, %1; cvt.u32.u64 %0, t; }" : "=r"(a) : "l"(p));
    return a;
}
#define CVTPK(r, lo, hi) asm("cvt.rn.satfinite.bf16x2.f32 %0, %1, %2;" : "=r"(r) : "f"(hi), "f"(lo))
#define LDSM4(r0, r1, r2, r3, a) \
    asm volatile("ldmatrix.sync.aligned.m8n8.x4.shared.b16 {%0,%1,%2,%3}, [%4];" \
        : "=r"(r0), "=r"(r1), "=r"(r2), "=r"(r3) : "r"(a))
#define MMA16816(c, a0, a1, a2, a3, b0, b1) \
    asm volatile("mma.sync.aligned.m16n8k16.row.col.f32.bf16.bf16.f32 " \
        "{%0,%1,%2,%3}, {%4,%5,%6,%7}, {%8,%9}, {%0,%1,%2,%3};" \
        : "+f"((c)[0]), "+f"((c)[1]), "+f"((c)[2]), "+f"((c)[3]) \
        : "r"(a0), "r"(a1), "r"(a2), "r"(a3), "r"(b0), "r"(b1))
#define CPA16(dst, src) asm volatile("cp.async.cg.shared.global [%0], [%1], 16;" :: "r"(dst), "l"(src) : "memory")
#define CPCOMMIT() asm volatile("cp.async.commit_group;" ::: "memory")
#define CPWAIT2()  asm volatile("cp.async.wait_group 2;" ::: "memory")

// ============ kernel 1: fused dispersion + GEMM + energy e_max stream ============
// grid (32, 8) = 256 CTAs, 2 CTAs/SM (all co-resident -> flag barrier is safe).
__global__ __launch_bounds__(256, 2) void k_gemm(const float* __restrict__ A,
                                                 const float* __restrict__ Vs,
                                                 const float* __restrict__ thick,
                                                 const float* __restrict__ periods,
                                                 const float* __restrict__ energy,
                                                 float* __restrict__ out) {
    extern __shared__ __align__(128) char smem[];
    __shared__ float w[NPERIODS][NLAYER];
    __shared__ float wsum[NPERIODS];
    __shared__ float zc[NLAYER];
    __shared__ float vsl[32 * 25];
    __shared__ float sred[8];
    uint32_t sb = smem_u32(smem);
    int tid = threadIdx.x, lane = tid & 31, wid = tid >> 5;
    int m0 = blockIdx.x * MT, k0 = blockIdx.y * KB;
    int cta = blockIdx.y * 32 + blockIdx.x;          // 0..255

    // ---- producer mappings ----
    int ar = tid >> 1, haf = tid & 1;
    int bn = tid >> 2, bg = tid & 3;
    const float* srcA0 = A + (size_t)(m0 + ar) * NGRID + k0 + haf * 16;
    const __nv_bfloat16* srcB0 = g_Rt + (size_t)bn * NGRID + k0 + bg * 8;
    uint32_t dA_row = (uint32_t)(ar * 128);
    uint32_t aXor = (uint32_t)((ar & 7) << 4);
    uint32_t dB = (uint32_t)(bn * 128) + (((uint32_t)bg << 4) ^ ((uint32_t)(bn & 7) << 4));

    // ---- consumer mappings ----
    int gid = lane >> 2, tig = lane & 3;
    uint32_t rowA0 = (uint32_t)((wid * 16 + gid) * 128);
    uint32_t rowA1 = rowA0 + 8 * 128;
    uint32_t sub = (uint32_t)((tig & 1) * 8);
    int gbase = tig >> 1;
    int li = lane >> 3, lr = lane & 7;
    int b_nb = ((li >> 1) << 3) + lr;
    uint32_t lb_row = (uint32_t)(b_nb * 128);
    uint32_t lb_xor = (uint32_t)((b_nb & 7) << 4);
    uint32_t lb_kh = (uint32_t)((li & 1) * 16);

    // ---- energy side-stream ----
    size_t ebase = (size_t)cta * EROWS_PER_CTA;
    float4 er[3][2];
    float msum = 0.0f;

    auto eload = [&](int c) {
        size_t r0 = ebase + (size_t)c * 25 + wid * 3;
#pragma unroll
        for (int j = 0; j < 3; j++) {
            const float4* e4 = (const float4*)(energy + (r0 + j) * NC);
            er[j][0] = e4[lane];
            er[j][1] = (lane < 18) ? e4[lane + 32]
                                   : make_float4(-1e30f, -1e30f, -1e30f, -1e30f);
        }
    };
    auto econsume = [&]() {
#pragma unroll
        for (int j = 0; j < 3; j++) {
            float4 a = er[j][0], b = er[j][1];
            float m = fmaxf(fmaxf(fmaxf(a.x, a.y), fmaxf(a.z, a.w)),
                            fmaxf(fmaxf(b.x, b.y), fmaxf(b.z, b.w)));
#pragma unroll
            for (int off = 16; off > 0; off >>= 1)
                m = fmaxf(m, __shfl_xor_sync(0xffffffffu, m, off));
            msum += m;
        }
    };

    float acc[8][4];
#pragma unroll
    for (int j = 0; j < 8; j++)
#pragma unroll
        for (int i = 0; i < 4; i++) acc[j][i] = 0.0f;

    auto issueA = [&](int c) {
        uint32_t buf = sb + (uint32_t)(c & (NSTAGE - 1)) * STAGE;
        const float* sA = srcA0 + c * KCHUNK;
#pragma unroll
        for (int i = 0; i < 4; i++) {
            uint32_t g = (uint32_t)(haf * 4 + i);
            CPA16(buf + dA_row + ((g << 4) ^ aXor), sA + i * 4);
        }
    };
    auto issueB = [&](int c) {
        uint32_t buf = sb + (uint32_t)(c & (NSTAGE - 1)) * STAGE;
        CPA16(buf + STAGE_A + dB, srcB0 + c * KCHUNK);
    };

    // ---- prologue part 1: A-only stages 0..2 (independent of Rt) + energy ----
#pragma unroll
    for (int s = 0; s < NSTAGE - 1; s++) { issueA(s); CPCOMMIT(); }
    eload(0);

    // ---- phase 0: dispersion slice for g in [cta*32, cta*32+32) ----
    {
        int g0 = cta * 32;
        if (tid == 0) {
            float c = 0.0f;
            for (int l = 0; l < NLAYER; l++) {
                float t = thick[l];
                zc[l] = c + 0.5f * t;
                c += t;
            }
        }
        __syncthreads();
        for (int idx = tid; idx < NPERIODS * NLAYER; idx += 256) {
            int p = idx / NLAYER, l = idx - p * NLAYER;
            float ds = VREF * periods[p] / 3.0f;
            w[p][l] = expf(-zc[l] / ds) * thick[l];
        }
        for (int idx = tid; idx < 32 * NLAYER; idx += 256) {
            int gl = idx / NLAYER, l = idx - gl * NLAYER;
            vsl[gl * 25 + l] = Vs[(g0 + gl) * NLAYER + l];
        }
        __syncthreads();
        if (tid < NPERIODS) {
            float s = 0.0f;
#pragma unroll
            for (int l = 0; l < NLAYER; l++) s += w[tid][l];
            wsum[tid] = s;
        }
        __syncthreads();
        int gl = tid & 31, pg = tid >> 5;
#pragma unroll 1
        for (int p = pg; p < NPAD; p += 8) {
            float val = 0.0f;
            if (p < NPERIODS) {
                float d = 0.0f;
#pragma unroll
                for (int l = 0; l < NLAYER; l++) d += w[p][l] * vsl[gl * 25 + l];
                val = wsum[p] / (RAYF * d);
            }
            g_Rt[p * NGRID + g0 + gl] = __float2bfloat16(val);
        }
        // publish + wait for all 256 slices (all CTAs co-resident: 256 <= 296 slots)
        __threadfence();
        __syncthreads();
        if (tid == 0) {
            atomicAdd(&g_flag, 1);
            while (*(volatile int*)&g_flag < NCTA) {}
        }
        __syncthreads();
        __threadfence();
    }

    // ---- prologue part 2: B for stages 0..2 (3 more groups; wait math unchanged) ----
#pragma unroll
    for (int s = 0; s < NSTAGE - 1; s++) { issueB(s); CPCOMMIT(); }

#pragma unroll 1
    for (int c = 0; c < NCHUNK; c++) {
        CPWAIT2();            // iter c: pending<=2 => A(c)+B(c) landed
        __syncthreads();
        if (c + NSTAGE - 1 < NCHUNK) { issueA(c + NSTAGE - 1); issueB(c + NSTAGE - 1); }
        CPCOMMIT();

        econsume();
        if (c + 1 < NCHUNK) eload(c + 1);

        uint32_t bufA = sb + (uint32_t)(c & (NSTAGE - 1)) * STAGE;
        uint32_t bufB = bufA + STAGE_A;
        const char* pA = smem + (size_t)(c & (NSTAGE - 1)) * STAGE;
#pragma unroll
        for (int ks = 0; ks < 2; ks++) {
            int gp0 = ks * 4 + gbase;
            uint32_t x0 = (uint32_t)((gp0 ^ gid) << 4);
            uint32_t x2 = (uint32_t)(((gp0 + 2) ^ gid) << 4);
            float2 v0 = *(const float2*)(pA + rowA0 + x0 + sub);
            float2 v1 = *(const float2*)(pA + rowA1 + x0 + sub);
            float2 v2 = *(const float2*)(pA + rowA0 + x2 + sub);
            float2 v3 = *(const float2*)(pA + rowA1 + x2 + sub);
            uint32_t a0, a1, a2, a3;
            CVTPK(a0, v0.x, v0.y);
            CVTPK(a1, v1.x, v1.y);
            CVTPK(a2, v2.x, v2.y);
            CVTPK(a3, v3.x, v3.y);
#pragma unroll
            for (int nt = 0; nt < 4; nt++) {
                uint32_t b0, b1, b2, b3;
                LDSM4(b0, b1, b2, b3,
                      bufB + (uint32_t)(nt * 2048) + lb_row +
                      (((uint32_t)(ks * 32) + lb_kh) ^ lb_xor));
                MMA16816(acc[2 * nt],     a0, a1, a2, a3, b0, b1);
                MMA16816(acc[2 * nt + 1], a0, a1, a2, a3, b2, b3);
            }
        }
    }

    // ---- energy epilogue: 25th row of each chunk (4 per warp) ----
#pragma unroll
    for (int t = 0; t < 4; t++) {
        size_t row = ebase + (size_t)(wid + t * 8) * 25 + 24;
        const float4* e4 = (const float4*)(energy + row * NC);
        float4 a = e4[lane];
        float4 b = (lane < 18) ? e4[lane + 32]
                               : make_float4(-1e30f, -1e30f, -1e30f, -1e30f);
        float m = fmaxf(fmaxf(fmaxf(a.x, a.y), fmaxf(a.z, a.w)),
                        fmaxf(fmaxf(b.x, b.y), fmaxf(b.z, b.w)));
#pragma unroll
        for (int off = 16; off > 0; off >>= 1)
            m = fmaxf(m, __shfl_xor_sync(0xffffffffu, m, off));
        msum += m;
    }
    if (lane == 0) sred[wid] = msum;

    // ---- GEMM epilogue ----
    int m = m0 + wid * 16 + gid;
    float* outp = g_part + ((size_t)blockIdx.y * NOBS + m) * NPAD;
#pragma unroll
    for (int j = 0; j < 8; j++) {
        *(float2*)(outp + j * 8 + tig * 2) = make_float2(acc[j][0], acc[j][1]);
        *(float2*)(outp + 8 * NPAD + j * 8 + tig * 2) = make_float2(acc[j][2], acc[j][3]);
    }
    __syncthreads();
    if (tid == 0) {
        float t = 0.0f;
#pragma unroll
        for (int i = 0; i < 8; i++) t += sred[i];
        atomicAdd(out, -t);                          // -Σ e_max
    }
}

// ============ kernel 2: interp-only finalize (block per obs) ============
__global__ __launch_bounds__(64) void k_interp(const float* __restrict__ energy,
                                               const float* __restrict__ c_axis,
                                               float* __restrict__ out) {
    __shared__ float cs[NC];
    __shared__ float sred[2];
    int o = blockIdx.x, t = threadIdx.x;

    for (int i = t; i < NC; i += 64) cs[i] = c_axis[(size_t)o * NC + i];
    float s = 0.0f;
    if (t < NPERIODS) {
#pragma unroll
        for (int kz = 0; kz < KSPLIT; kz++)
            s += g_part[((size_t)kz * NOBS + o) * NPAD + t];
    }
    __syncthreads();

    float contrib = 0.0f;
    if (t < NPERIODS) {
        float v = 1.0f / s;                  // c_pred
        int lo = 0, hi = NC;                 // searchsorted-left on smem row
        while (lo < hi) {
            int mid = (lo + hi) >> 1;
            if (cs[mid] < v) lo = mid + 1; else hi = mid;
        }
        int idx = lo < 1 ? 1 : (lo > NC - 1 ? NC - 1 : lo);
        float c0 = cs[idx - 1], c1 = cs[idx];
        const float* e = energy + ((size_t)o * NPERIODS + t) * NC;
        float e0 = e[idx - 1], e1 = e[idx];
        float wgt = (v - c0) / (c1 - c0 + 1e-12f);
        contrib = e0 + wgt * (e1 - e0);      // +e_interp
    }
#pragma unroll
    for (int off = 16; off > 0; off >>= 1)
        contrib += __shfl_xor_sync(0xffffffffu, contrib, off);
    if ((t & 31) == 0) sred[t >> 5] = contrib;
    __syncthreads();
    if (t == 0) atomicAdd(out, sred[0] + sred[1]);   // Σ e_interp (joins -Σ e_max)
}

extern "C" void kernel_launch(void* const* d_in, const int* in_sizes, int n_in,
                              void* d_out, int out_size) {
    const float* Vs      = (const float*)d_in[0];
    const float* A       = (const float*)d_in[1];
    const float* energy  = (const float*)d_in[2];
    const float* c_axis  = (const float*)d_in[3];
    const float* thick   = (const float*)d_in[4];
    const float* periods = (const float*)d_in[5];
    float* out = (float*)d_out;

    cudaFuncSetAttribute(k_gemm, cudaFuncAttributeMaxDynamicSharedMemorySize, SMEM_TOT);

    void* flag_ptr = nullptr;
    cudaGetSymbolAddress(&flag_ptr, g_flag);
    cudaMemsetAsync(flag_ptr, 0, sizeof(int));       // reset barrier each replay
    cudaMemsetAsync(out, 0, sizeof(float));
    k_gemm<<<dim3(NOBS / MT, KSPLIT), 256, SMEM_TOT>>>(A, Vs, thick, periods, energy, out);
    k_interp<<<NOBS, 64>>>(energy, c_axis, out);
}

// round 15
// speedup vs baseline: 1.0706x; 1.0706x over previous
#include <cuda_runtime.h>
#include <cuda_bf16.h>
#include <cstdint>

#define NGRID 8192
#define NLAYER 24
#define NPERIODS 50
#define NOBS 4096
#define NC 200
#define NPAD 64
#define KSPLIT 8
#define KB (NGRID / KSPLIT)      // 1024 K per CTA
#define KCHUNK 32
#define NCHUNK (KB / KCHUNK)     // 32
#define MT 128
#define NSTAGE 4
#define STAGE_A (MT * 128)           // 128 rows x 128B (32 f32)
#define STAGE_B (NPAD * 128)         // 64 rows x 128B (32 bf16 used)
#define STAGE (STAGE_A + STAGE_B)    // 24576
#define SMEM_TOT (NSTAGE * STAGE)    // 98304 -> 2 CTAs/SM
#define EROWS_PER_CTA 800            // 204800 / 256
#define VREF 3.0f
#define RAYF 0.92f

// ---------------- scratch (no allocation allowed) ----------------
__device__ __nv_bfloat16 g_Rt[NPAD * NGRID];    // [n=64][k=8192] bf16; rows 50..63 zero
__device__ float g_part[NOBS * KSPLIT * NPAD];  // [o][kz][p]: partials for one (o,p) within 2KB

// ---------------- helpers ----------------
__device__ __forceinline__ uint32_t smem_u32(const void* p) {
    uint32_t a;
    asm("{ .reg .u64 t; cvta.to.shared.u64 t, %1; cvt.u32.u64 %0, t; }" : "=r"(a) : "l"(p));
    return a;
}
#define CVTPK(r, lo, hi) asm("cvt.rn.satfinite.bf16x2.f32 %0, %1, %2;" : "=r"(r) : "f"(hi), "f"(lo))
#define LDSM4(r0, r1, r2, r3, a) \
    asm volatile("ldmatrix.sync.aligned.m8n8.x4.shared.b16 {%0,%1,%2,%3}, [%4];" \
        : "=r"(r0), "=r"(r1), "=r"(r2), "=r"(r3) : "r"(a))
#define MMA16816(c, a0, a1, a2, a3, b0, b1) \
    asm volatile("mma.sync.aligned.m16n8k16.row.col.f32.bf16.bf16.f32 " \
        "{%0,%1,%2,%3}, {%4,%5,%6,%7}, {%8,%9}, {%0,%1,%2,%3};" \
        : "+f"((c)[0]), "+f"((c)[1]), "+f"((c)[2]), "+f"((c)[3]) \
        : "r"(a0), "r"(a1), "r"(a2), "r"(a3), "r"(b0), "r"(b1))
#define CPA16(dst, src) asm volatile("cp.async.cg.shared.global [%0], [%1], 16;" :: "r"(dst), "l"(src) : "memory")
#define CPCOMMIT() asm volatile("cp.async.commit_group;" ::: "memory")
#define CPWAIT2()  asm volatile("cp.async.wait_group 2;" ::: "memory")

// ============ kernel 1: dispersion surrogate (vs-in-regs, 4-p-blocked) ============
__global__ __launch_bounds__(256) void k_dispersion(const float* __restrict__ Vs,
                                                    const float* __restrict__ thick,
                                                    const float* __restrict__ periods,
                                                    float* __restrict__ out) {
    __shared__ float w[NPERIODS][NLAYER];
    __shared__ float wsum[NPERIODS];
    __shared__ float zc[NLAYER];
    __shared__ float vsm[32 * 25];
    int tid = threadIdx.x;
    int g0 = blockIdx.x * 32;

    if (tid == 0) {
        float c = 0.0f;
        for (int l = 0; l < NLAYER; l++) {
            float t = thick[l];
            zc[l] = c + 0.5f * t;
            c += t;
        }
        if (blockIdx.x == 0) out[0] = 0.0f;       // later kernels accumulate into out
    }
    __syncthreads();

    for (int idx = tid; idx < NPERIODS * NLAYER; idx += 256) {
        int p = idx / NLAYER, l = idx - p * NLAYER;
        float ds = VREF * periods[p] / 3.0f;
        w[p][l] = __expf(-zc[l] / ds) * thick[l];
    }
    for (int idx = tid; idx < 32 * NLAYER; idx += 256) {
        int gl = idx / NLAYER, l = idx - gl * NLAYER;
        vsm[gl * 25 + l] = Vs[(g0 + gl) * NLAYER + l];
    }
    __syncthreads();
    if (tid < NPERIODS) {
        float s = 0.0f;
#pragma unroll
        for (int l = 0; l < NLAYER; l++) s += w[tid][l];
        wsum[tid] = s;
    }
    __syncthreads();

    int gl = tid & 31, pg = tid >> 5;
    float vr[NLAYER];
#pragma unroll
    for (int l = 0; l < NLAYER; l++) vr[l] = vsm[gl * 25 + l];   // vs -> registers (once)

#pragma unroll
    for (int blk = 0; blk < 2; blk++) {           // 4 p-chains per block iter
        int p0 = pg + blk * 32;                   // p0, p0+8, p0+16, p0+24
        float d[4] = {0.0f, 0.0f, 0.0f, 0.0f};
#pragma unroll
        for (int l = 0; l < NLAYER; l++) {
            float x = vr[l];
            d[0] += w[(p0      ) < NPERIODS ? (p0      ) : 0][l] * x;
            d[1] += w[(p0 +  8) < NPERIODS ? (p0 +  8) : 0][l] * x;
            d[2] += w[(p0 + 16) < NPERIODS ? (p0 + 16) : 0][l] * x;
            d[3] += w[(p0 + 24) < NPERIODS ? (p0 + 24) : 0][l] * x;
        }
#pragma unroll
        for (int j = 0; j < 4; j++) {
            int p = p0 + j * 8;
            float val = (p < NPERIODS) ? wsum[p] / (RAYF * d[j]) : 0.0f;
            g_Rt[p * NGRID + g0 + gl] = __float2bfloat16(val);
        }
    }
}

// ============ kernel 2: R12 GEMM + interleaved energy e_max stream ============
// grid (32, 8) = 256 CTAs, 256 threads, 2 CTAs/SM.
__global__ __launch_bounds__(256, 2) void k_gemm(const float* __restrict__ A,
                                                 const float* __restrict__ energy,
                                                 float* __restrict__ out) {
    extern __shared__ __align__(128) char smem[];
    __shared__ float sred[8];
    uint32_t sb = smem_u32(smem);
    int tid = threadIdx.x, lane = tid & 31, wid = tid >> 5;
    int m0 = blockIdx.x * MT, k0 = blockIdx.y * KB;

    // ---- producer mappings ----
    int ar = tid >> 1, haf = tid & 1;
    int bn = tid >> 2, bg = tid & 3;
    const float* srcA0 = A + (size_t)(m0 + ar) * NGRID + k0 + haf * 16;
    const __nv_bfloat16* srcB0 = g_Rt + (size_t)bn * NGRID + k0 + bg * 8;
    uint32_t dA_row = (uint32_t)(ar * 128);
    uint32_t aXor = (uint32_t)((ar & 7) << 4);
    uint32_t dB = (uint32_t)(bn * 128) + (((uint32_t)bg << 4) ^ ((uint32_t)(bn & 7) << 4));

    // ---- consumer mappings ----
    int gid = lane >> 2, tig = lane & 3;
    uint32_t rowA0 = (uint32_t)((wid * 16 + gid) * 128);
    uint32_t rowA1 = rowA0 + 8 * 128;
    uint32_t sub = (uint32_t)((tig & 1) * 8);
    int gbase = tig >> 1;
    int li = lane >> 3, lr = lane & 7;
    int b_nb = ((li >> 1) << 3) + lr;
    uint32_t lb_row = (uint32_t)(b_nb * 128);
    uint32_t lb_xor = (uint32_t)((b_nb & 7) << 4);
    uint32_t lb_kh = (uint32_t)((li & 1) * 16);

    // ---- energy side-stream ----
    int ecta = blockIdx.y * 32 + blockIdx.x;
    size_t ebase = (size_t)ecta * EROWS_PER_CTA;
    float4 er[3][2];
    float msum = 0.0f;

    auto eload = [&](int c) {
        size_t r0 = ebase + (size_t)c * 25 + wid * 3;
#pragma unroll
        for (int j = 0; j < 3; j++) {
            const float4* e4 = (const float4*)(energy + (r0 + j) * NC);
            er[j][0] = e4[lane];
            er[j][1] = (lane < 18) ? e4[lane + 32]
                                   : make_float4(-1e30f, -1e30f, -1e30f, -1e30f);
        }
    };
    auto econsume = [&]() {
#pragma unroll
        for (int j = 0; j < 3; j++) {
            float4 a = er[j][0], b = er[j][1];
            float m = fmaxf(fmaxf(fmaxf(a.x, a.y), fmaxf(a.z, a.w)),
                            fmaxf(fmaxf(b.x, b.y), fmaxf(b.z, b.w)));
#pragma unroll
            for (int off = 16; off > 0; off >>= 1)
                m = fmaxf(m, __shfl_xor_sync(0xffffffffu, m, off));
            msum += m;
        }
    };

    float acc[8][4];
#pragma unroll
    for (int j = 0; j < 8; j++)
#pragma unroll
        for (int i = 0; i < 4; i++) acc[j][i] = 0.0f;

    auto issue = [&](int c) {
        uint32_t buf = sb + (uint32_t)(c & (NSTAGE - 1)) * STAGE;
        const float* sA = srcA0 + c * KCHUNK;
#pragma unroll
        for (int i = 0; i < 4; i++) {
            uint32_t g = (uint32_t)(haf * 4 + i);
            CPA16(buf + dA_row + ((g << 4) ^ aXor), sA + i * 4);
        }
        CPA16(buf + STAGE_A + dB, srcB0 + c * KCHUNK);
    };

#pragma unroll
    for (int s = 0; s < NSTAGE - 1; s++) { issue(s); CPCOMMIT(); }
    eload(0);

#pragma unroll 1
    for (int c = 0; c < NCHUNK; c++) {
        CPWAIT2();
        __syncthreads();
        if (c + NSTAGE - 1 < NCHUNK) issue(c + NSTAGE - 1);
        CPCOMMIT();

        econsume();
        if (c + 1 < NCHUNK) eload(c + 1);

        uint32_t bufA = sb + (uint32_t)(c & (NSTAGE - 1)) * STAGE;
        uint32_t bufB = bufA + STAGE_A;
        const char* pA = smem + (size_t)(c & (NSTAGE - 1)) * STAGE;
#pragma unroll
        for (int ks = 0; ks < 2; ks++) {
            int gp0 = ks * 4 + gbase;
            uint32_t x0 = (uint32_t)((gp0 ^ gid) << 4);
            uint32_t x2 = (uint32_t)(((gp0 + 2) ^ gid) << 4);
            float2 v0 = *(const float2*)(pA + rowA0 + x0 + sub);
            float2 v1 = *(const float2*)(pA + rowA1 + x0 + sub);
            float2 v2 = *(const float2*)(pA + rowA0 + x2 + sub);
            float2 v3 = *(const float2*)(pA + rowA1 + x2 + sub);
            uint32_t a0, a1, a2, a3;
            CVTPK(a0, v0.x, v0.y);
            CVTPK(a1, v1.x, v1.y);
            CVTPK(a2, v2.x, v2.y);
            CVTPK(a3, v3.x, v3.y);
#pragma unroll
            for (int nt = 0; nt < 4; nt++) {
                uint32_t b0, b1, b2, b3;
                LDSM4(b0, b1, b2, b3,
                      bufB + (uint32_t)(nt * 2048) + lb_row +
                      (((uint32_t)(ks * 32) + lb_kh) ^ lb_xor));
                MMA16816(acc[2 * nt],     a0, a1, a2, a3, b0, b1);
                MMA16816(acc[2 * nt + 1], a0, a1, a2, a3, b2, b3);
            }
        }
    }

    // ---- energy epilogue: 25th row of each chunk (4 per warp) ----
#pragma unroll
    for (int t = 0; t < 4; t++) {
        size_t row = ebase + (size_t)(wid + t * 8) * 25 + 24;
        const float4* e4 = (const float4*)(energy + row * NC);
        float4 a = e4[lane];
        float4 b = (lane < 18) ? e4[lane + 32]
                               : make_float4(-1e30f, -1e30f, -1e30f, -1e30f);
        float m = fmaxf(fmaxf(fmaxf(a.x, a.y), fmaxf(a.z, a.w)),
                        fmaxf(fmaxf(b.x, b.y), fmaxf(b.z, b.w)));
#pragma unroll
        for (int off = 16; off > 0; off >>= 1)
            m = fmaxf(m, __shfl_xor_sync(0xffffffffu, m, off));
        msum += m;
    }
    if (lane == 0) sred[wid] = msum;

    // ---- GEMM epilogue: g_part layout [o][kz][p] ----
    int m = m0 + wid * 16 + gid;
    float* outp = g_part + (size_t)m * (KSPLIT * NPAD) + blockIdx.y * NPAD;
#pragma unroll
    for (int j = 0; j < 8; j++) {
        *(float2*)(outp + j * 8 + tig * 2) = make_float2(acc[j][0], acc[j][1]);
        *(float2*)(outp + (size_t)8 * (KSPLIT * NPAD) + j * 8 + tig * 2) =
            make_float2(acc[j][2], acc[j][3]);
    }
    __syncthreads();
    if (tid == 0) {
        float t = 0.0f;
#pragma unroll
        for (int i = 0; i < 8; i++) t += sred[i];
        atomicAdd(out, -t);                       // -Σ e_max
    }
}

// ============ kernel 3: interp-only finalize (block per obs) ============
__global__ __launch_bounds__(64) void k_interp(const float* __restrict__ energy,
                                               const float* __restrict__ c_axis,
                                               float* __restrict__ out) {
    __shared__ float cs[NC];
    __shared__ float sred[2];
    int o = blockIdx.x, t = threadIdx.x;

    for (int i = t; i < NC; i += 64) cs[i] = c_axis[(size_t)o * NC + i];
    float s = 0.0f;
    if (t < NPERIODS) {
        const float* pp = g_part + (size_t)o * (KSPLIT * NPAD) + t;   // 8 partials within 2KB
#pragma unroll
        for (int kz = 0; kz < KSPLIT; kz++) s += pp[kz * NPAD];
    }
    __syncthreads();

    float contrib = 0.0f;
    if (t < NPERIODS) {
        float v = 1.0f / s;                  // c_pred
        int lo = 0, hi = NC;                 // searchsorted-left on smem row
        while (lo < hi) {
            int mid = (lo + hi) >> 1;
            if (cs[mid] < v) lo = mid + 1; else hi = mid;
        }
        int idx = lo < 1 ? 1 : (lo > NC - 1 ? NC - 1 : lo);
        float c0 = cs[idx - 1], c1 = cs[idx];
        const float* e = energy + ((size_t)o * NPERIODS + t) * NC;
        float e0 = e[idx - 1], e1 = e[idx];
        float wgt = (v - c0) / (c1 - c0 + 1e-12f);
        contrib = e0 + wgt * (e1 - e0);      // +e_interp
    }
#pragma unroll
    for (int off = 16; off > 0; off >>= 1)
        contrib += __shfl_xor_sync(0xffffffffu, contrib, off);
    if ((t & 31) == 0) sred[t >> 5] = contrib;
    __syncthreads();
    if (t == 0) atomicAdd(out, sred[0] + sred[1]);   // Σ e_interp (joins -Σ e_max)
}

extern "C" void kernel_launch(void* const* d_in, const int* in_sizes, int n_in,
                              void* d_out, int out_size) {
    const float* Vs      = (const float*)d_in[0];
    const float* A       = (const float*)d_in[1];
    const float* energy  = (const float*)d_in[2];
    const float* c_axis  = (const float*)d_in[3];
    const float* thick   = (const float*)d_in[4];
    const float* periods = (const float*)d_in[5];
    float* out = (float*)d_out;

    cudaFuncSetAttribute(k_gemm, cudaFuncAttributeMaxDynamicSharedMemorySize, SMEM_TOT);

    k_dispersion<<<NGRID / 32, 256>>>(Vs, thick, periods, out);
    k_gemm<<<dim3(NOBS / MT, KSPLIT), 256, SMEM_TOT>>>(A, energy, out);
    k_interp<<<NOBS, 64>>>(energy, c_axis, out);
}